// round 7
// baseline (speedup 1.0000x reference)
#include <cuda_runtime.h>

#define N_NODES 100000
#define F_IN    256
#define F_HID   64
#define F_OUT   40

// Scratch (static device globals — no allocation allowed)
__device__ float g_dis[N_NODES];              // deg accumulator, then rsqrt(deg+1)
__device__ float g_h1[N_NODES * F_HID];       // x @ W1
__device__ float g_agg1[N_NODES * F_HID];     // aggregated layer-1, then relu(...)
__device__ float g_h2[N_NODES * F_OUT];       // relu_out @ W2

// ---------------------------------------------------------------------------
// Packed f32x2 helpers (Blackwell FFMA2 path)
// ---------------------------------------------------------------------------
__device__ __forceinline__ unsigned long long f2pack(float lo, float hi) {
    unsigned long long r;
    asm("mov.b64 %0, {%1, %2};" : "=l"(r) : "f"(lo), "f"(hi));
    return r;
}
__device__ __forceinline__ void f2unpack(unsigned long long v, float& lo, float& hi) {
    asm("mov.b64 {%0, %1}, %2;" : "=f"(lo), "=f"(hi) : "l"(v));
}
__device__ __forceinline__ void fma2(unsigned long long& d,
                                     unsigned long long a, unsigned long long b) {
    asm("fma.rn.f32x2 %0, %1, %2, %0;" : "+l"(d) : "l"(a), "l"(b));
}
// load 16B of smem as two packed f32x2 (zero pack cost)
__device__ __forceinline__ void lds_v2u64(unsigned long long& a, unsigned long long& b,
                                          const void* p) {
    unsigned s = (unsigned)__cvta_generic_to_shared(p);
    asm volatile("ld.shared.v2.u64 {%0, %1}, [%2];" : "=l"(a), "=l"(b) : "r"(s));
}

// ---------------------------------------------------------------------------
// Degree / normalization
// ---------------------------------------------------------------------------
__global__ void k_zero_deg(int n) {
    int i = blockIdx.x * blockDim.x + threadIdx.x;
    if (i < n) g_dis[i] = 0.0f;
}

__global__ void k_deg(const int* __restrict__ ei,
                      const float* __restrict__ ew, int E) {
    int e = blockIdx.x * blockDim.x + threadIdx.x;
    if (e < E) {
        int c = ei[E + e];
        atomicAdd(&g_dis[c], ew[e]);
    }
}

__global__ void k_dis(int n) {
    int i = blockIdx.x * blockDim.x + threadIdx.x;
    if (i < n) g_dis[i] = rsqrtf(g_dis[i] + 1.0f);   // +1 = self-loop weight
}

// ---------------------------------------------------------------------------
// GEMM1: g_h1[N,64] = x[N,256] @ W1[256,64]
// 256 thr, tile 256 rows x 64 cols, each thread 8x8 via FFMA2 row-pairs:
// per k-step: 4x LDS.128 + 8 packs + 32 FMA2 (= 64 FMA). 1.0 B LDS / FMA.
// Epilogue also zeroes g_agg1 (saves a separate 25.6 MB pass).
// ---------------------------------------------------------------------------
#define G1_ROWS 256
#define G1_KCH  32

__global__ void k_gemm1(const float* __restrict__ x,
                        const float* __restrict__ W1) {
    __shared__ float xs[G1_KCH][G1_ROWS];   // 32 KB, k-major
    __shared__ float ws[G1_KCH][F_HID];     // 8 KB,  k-major

    int t    = threadIdx.x;
    int row0 = blockIdx.x * G1_ROWS;
    int tx   = t & 7;         // col group: cols tx*8 .. +7
    int ty   = t >> 3;        // row group: rows ty*8 .. +7

    // acc2[p][j]: rows (ty*8+2p, ty*8+2p+1), col tx*8+j, packed f32x2
    unsigned long long acc2[4][8];
    #pragma unroll
    for (int p = 0; p < 4; p++)
        #pragma unroll
        for (int j = 0; j < 8; j++) acc2[p][j] = f2pack(0.0f, 0.0f);

    for (int kc = 0; kc < F_IN / G1_KCH; kc++) {
        // W chunk: 32x64 floats = 512 float4 (W1 is k-major already)
        const float4* w4 = (const float4*)(W1 + kc * G1_KCH * F_HID);
        ((float4*)ws)[t]       = w4[t];
        ((float4*)ws)[t + 256] = w4[t + 256];
        // x tile: 256 rows x 32 k = 2048 float4, transposed into xs[k][row]
        #pragma unroll
        for (int j = 0; j < 8; j++) {
            int idx = t + j * 256;
            int r   = idx & 255;
            int kq  = idx >> 8;                  // 0..7
            int gr  = row0 + r;
            if (gr >= N_NODES) gr = N_NODES - 1; // clamped read (result discarded)
            float4 v = *(const float4*)(x + (size_t)gr * F_IN + kc * G1_KCH + kq * 4);
            xs[kq * 4 + 0][r] = v.x;
            xs[kq * 4 + 1][r] = v.y;
            xs[kq * 4 + 2][r] = v.z;
            xs[kq * 4 + 3][r] = v.w;
        }
        __syncthreads();

        #pragma unroll
        for (int kk = 0; kk < G1_KCH; kk++) {
            unsigned long long ap0, ap1, ap2, ap3;
            lds_v2u64(ap0, ap1, &xs[kk][ty * 8]);
            lds_v2u64(ap2, ap3, &xs[kk][ty * 8 + 4]);
            float4 b0 = *(const float4*)&ws[kk][tx * 8];
            float4 b1 = *(const float4*)&ws[kk][tx * 8 + 4];
            unsigned long long bd[8];
            bd[0] = f2pack(b0.x, b0.x); bd[1] = f2pack(b0.y, b0.y);
            bd[2] = f2pack(b0.z, b0.z); bd[3] = f2pack(b0.w, b0.w);
            bd[4] = f2pack(b1.x, b1.x); bd[5] = f2pack(b1.y, b1.y);
            bd[6] = f2pack(b1.z, b1.z); bd[7] = f2pack(b1.w, b1.w);
            #pragma unroll
            for (int j = 0; j < 8; j++) {
                fma2(acc2[0][j], ap0, bd[j]);
                fma2(acc2[1][j], ap1, bd[j]);
                fma2(acc2[2][j], ap2, bd[j]);
                fma2(acc2[3][j], ap3, bd[j]);
            }
        }
        __syncthreads();
    }

    const float4 z4 = make_float4(0.f, 0.f, 0.f, 0.f);
    #pragma unroll
    for (int p = 0; p < 4; p++) {
        float lo[8], hi[8];
        #pragma unroll
        for (int j = 0; j < 8; j++) f2unpack(acc2[p][j], lo[j], hi[j]);
        int gr0 = row0 + ty * 8 + 2 * p;
        if (gr0 < N_NODES) {
            float* o = g_h1 + (size_t)gr0 * F_HID + tx * 8;
            *(float4*)(o)     = make_float4(lo[0], lo[1], lo[2], lo[3]);
            *(float4*)(o + 4) = make_float4(lo[4], lo[5], lo[6], lo[7]);
            float* a = g_agg1 + (size_t)gr0 * F_HID + tx * 8;
            *(float4*)(a) = z4; *(float4*)(a + 4) = z4;
        }
        if (gr0 + 1 < N_NODES) {
            float* o = g_h1 + (size_t)(gr0 + 1) * F_HID + tx * 8;
            *(float4*)(o)     = make_float4(hi[0], hi[1], hi[2], hi[3]);
            *(float4*)(o + 4) = make_float4(hi[4], hi[5], hi[6], hi[7]);
            float* a = g_agg1 + (size_t)(gr0 + 1) * F_HID + tx * 8;
            *(float4*)(a) = z4; *(float4*)(a + 4) = z4;
        }
    }
}

// ---------------------------------------------------------------------------
// Layer-1 edge aggregation: 16 threads per edge, float4 vectorized atomics
// ---------------------------------------------------------------------------
__global__ void k_agg1(const int* __restrict__ ei,
                       const float* __restrict__ ew, int E) {
    int idx = blockIdx.x * blockDim.x + threadIdx.x;
    int e = idx >> 4;
    int c = idx & 15;
    if (e >= E) return;
    int r   = ei[e];
    int col = ei[E + e];
    float nrm = g_dis[r] * ew[e] * g_dis[col];
    float4 v = *(const float4*)(g_h1 + (size_t)r * F_HID + c * 4);
    atomicAdd((float4*)(g_agg1 + (size_t)col * F_HID + c * 4),
              make_float4(nrm * v.x, nrm * v.y, nrm * v.z, nrm * v.w));
}

// self loop + bias + relu, in place into g_agg1 (float4)
__global__ void k_selfrelu(const float* __restrict__ b1, int n4) {
    int idx4 = blockIdx.x * blockDim.x + threadIdx.x;
    if (idx4 >= n4) return;
    int i  = idx4 >> 4;          // node (16 float4 per row)
    int f4 = idx4 & 15;
    float d = g_dis[i];
    float s = d * d;
    float4 a = ((const float4*)g_agg1)[idx4];
    float4 h = ((const float4*)g_h1)[idx4];
    float4 b = ((const float4*)b1)[f4];
    float4 o;
    o.x = fmaxf(a.x + s * h.x + b.x, 0.0f);
    o.y = fmaxf(a.y + s * h.y + b.y, 0.0f);
    o.z = fmaxf(a.z + s * h.z + b.z, 0.0f);
    o.w = fmaxf(a.w + s * h.w + b.w, 0.0f);
    ((float4*)g_agg1)[idx4] = o;
}

// ---------------------------------------------------------------------------
// GEMM2: g_h2[N,40] = relu_out[N,64] @ W2[64,40]
// 256 thr, tile 128 rows x 40 cols, each thread 4x5 via FFMA2 row-pairs.
// ---------------------------------------------------------------------------
#define G2_ROWS 128

__global__ void k_gemm2(const float* __restrict__ W2) {
    __shared__ float rs[F_HID][G2_ROWS];   // 32 KB, k-major
    __shared__ float ws2[F_HID][F_OUT];    // 10 KB

    int t    = threadIdx.x;
    int row0 = blockIdx.x * G2_ROWS;
    int tx   = t & 7;         // col group: cols tx*5 .. +4
    int ty   = t >> 3;        // row group: rows ty*4 .. +3

    // load W2 (2560 floats = 640 float4)
    #pragma unroll
    for (int j = 0; j < 3; j++) {
        int i = t + j * 256;
        if (i < 640) ((float4*)ws2)[i] = ((const float4*)W2)[i];
    }
    // load relu tile: 128 rows x 64 k = 2048 float4, transposed
    #pragma unroll
    for (int j = 0; j < 8; j++) {
        int idx = t + j * 256;
        int r   = idx & 127;
        int kq  = idx >> 7;                   // 0..15
        int gr  = row0 + r;
        if (gr >= N_NODES) gr = N_NODES - 1;
        float4 v = *(const float4*)(g_agg1 + (size_t)gr * F_HID + kq * 4);
        rs[kq * 4 + 0][r] = v.x;
        rs[kq * 4 + 1][r] = v.y;
        rs[kq * 4 + 2][r] = v.z;
        rs[kq * 4 + 3][r] = v.w;
    }
    __syncthreads();

    // acc2[p][j]: rows (ty*4+2p, ty*4+2p+1), col tx*5+j
    unsigned long long acc2[2][5];
    #pragma unroll
    for (int p = 0; p < 2; p++)
        #pragma unroll
        for (int j = 0; j < 5; j++) acc2[p][j] = f2pack(0.0f, 0.0f);

    #pragma unroll
    for (int kk = 0; kk < F_HID; kk++) {
        unsigned long long ap0, ap1;
        lds_v2u64(ap0, ap1, &rs[kk][ty * 4]);
        const float* wrow = &ws2[kk][tx * 5];
        #pragma unroll
        for (int j = 0; j < 5; j++) {
            float bj = wrow[j];
            unsigned long long bd = f2pack(bj, bj);
            fma2(acc2[0][j], ap0, bd);
            fma2(acc2[1][j], ap1, bd);
        }
    }

    #pragma unroll
    for (int p = 0; p < 2; p++) {
        float lo[5], hi[5];
        #pragma unroll
        for (int j = 0; j < 5; j++) f2unpack(acc2[p][j], lo[j], hi[j]);
        int gr0 = row0 + ty * 4 + 2 * p;
        if (gr0 < N_NODES) {
            float* o = g_h2 + (size_t)gr0 * F_OUT + tx * 5;
            #pragma unroll
            for (int j = 0; j < 5; j++) o[j] = lo[j];
        }
        if (gr0 + 1 < N_NODES) {
            float* o = g_h2 + (size_t)(gr0 + 1) * F_OUT + tx * 5;
            #pragma unroll
            for (int j = 0; j < 5; j++) o[j] = hi[j];
        }
    }
}

// init output with bias + self-loop contribution (float4, 10 per row)
__global__ void k_init_out(const float* __restrict__ b2,
                           float* __restrict__ out, int n4) {
    int idx4 = blockIdx.x * blockDim.x + threadIdx.x;
    if (idx4 >= n4) return;
    int i  = idx4 / 10;
    int f4 = idx4 - i * 10;
    float d = g_dis[i];
    float s = d * d;
    float4 h = ((const float4*)g_h2)[idx4];
    float4 b = ((const float4*)b2)[f4];
    ((float4*)out)[idx4] =
        make_float4(b.x + s * h.x, b.y + s * h.y, b.z + s * h.z, b.w + s * h.w);
}

// Layer-2 edge aggregation: 10 float4 per edge
__global__ void k_agg2(const int* __restrict__ ei,
                       const float* __restrict__ ew,
                       float* __restrict__ out, int E) {
    int idx = blockIdx.x * blockDim.x + threadIdx.x;
    int e = idx / 10;
    int c = idx - e * 10;
    if (e >= E) return;
    int r   = ei[e];
    int col = ei[E + e];
    float nrm = g_dis[r] * ew[e] * g_dis[col];
    float4 v = *(const float4*)(g_h2 + (size_t)r * F_OUT + c * 4);
    atomicAdd((float4*)(out + (size_t)col * F_OUT + c * 4),
              make_float4(nrm * v.x, nrm * v.y, nrm * v.z, nrm * v.w));
}

// ---------------------------------------------------------------------------
extern "C" void kernel_launch(void* const* d_in, const int* in_sizes, int n_in,
                              void* d_out, int out_size) {
    const float* x  = (const float*)d_in[0];
    const int*   ei = (const int*)d_in[1];
    const float* ew = (const float*)d_in[2];
    const float* W1 = (const float*)d_in[3];
    const float* b1 = (const float*)d_in[4];
    const float* W2 = (const float*)d_in[5];
    const float* b2 = (const float*)d_in[6];
    float* out = (float*)d_out;

    int N = in_sizes[0] / F_IN;     // 100000
    int E = in_sizes[2];            // 1600000

    k_zero_deg<<<(N + 255) / 256, 256>>>(N);
    k_deg<<<(E + 255) / 256, 256>>>(ei, ew, E);
    k_dis<<<(N + 255) / 256, 256>>>(N);

    k_gemm1<<<(N + G1_ROWS - 1) / G1_ROWS, 256>>>(x, W1);   // also zeroes g_agg1

    {
        long long items = (long long)E * 16;
        k_agg1<<<(int)((items + 255) / 256), 256>>>(ei, ew, E);
    }
    int n1_4 = N * F_HID / 4;
    k_selfrelu<<<(n1_4 + 255) / 256, 256>>>(b1, n1_4);

    k_gemm2<<<(N + G2_ROWS - 1) / G2_ROWS, 256>>>(W2);

    int n2_4 = N * F_OUT / 4;
    k_init_out<<<(n2_4 + 255) / 256, 256>>>(b2, out, n2_4);
    {
        long long items = (long long)E * 10;
        k_agg2<<<(int)((items + 255) / 256), 256>>>(ei, ew, out, E);
    }
}

// round 8
// speedup vs baseline: 1.2263x; 1.2263x over previous
#include <cuda_runtime.h>

#define N_NODES  100000
#define F_IN     256
#define F_HID    64
#define F_OUT    40
#define EDGE_MAX 1700000

// Scratch (static device globals — no allocation allowed)
__device__ float  g_dis[N_NODES];             // rsqrt(weighted deg + 1)
__device__ float  g_deg[N_NODES];             // weighted degree accumulator
__device__ int    g_cnt[N_NODES];             // edges per destination
__device__ int    g_excl[N_NODES];            // local exclusive scan
__device__ int    g_bsum[512];                // per-block totals
__device__ int    g_boff[512];                // exclusive scan of block totals
__device__ int    g_rowptr[N_NODES];          // CSR row starts
__device__ int    g_fill[N_NODES];            // fill cursors
__device__ float2 g_edge[EDGE_MAX];           // (src as int bits, nrm)
__device__ float  g_h1[N_NODES * F_HID];      // x @ W1
__device__ float  g_agg1[N_NODES * F_HID];    // relu(agg + self + b1)
__device__ float  g_h2[N_NODES * F_OUT];      // relu_out @ W2

// ---------------------------------------------------------------------------
// Packed f32x2 helpers (Blackwell FFMA2 path)
// ---------------------------------------------------------------------------
__device__ __forceinline__ unsigned long long f2pack(float lo, float hi) {
    unsigned long long r;
    asm("mov.b64 %0, {%1, %2};" : "=l"(r) : "f"(lo), "f"(hi));
    return r;
}
__device__ __forceinline__ void f2unpack(unsigned long long v, float& lo, float& hi) {
    asm("mov.b64 {%0, %1}, %2;" : "=f"(lo), "=f"(hi) : "l"(v));
}
__device__ __forceinline__ void fma2(unsigned long long& d,
                                     unsigned long long a, unsigned long long b) {
    asm("fma.rn.f32x2 %0, %1, %2, %0;" : "+l"(d) : "l"(a), "l"(b));
}
__device__ __forceinline__ void lds_v2u64(unsigned long long& a, unsigned long long& b,
                                          const void* p) {
    unsigned s = (unsigned)__cvta_generic_to_shared(p);
    asm volatile("ld.shared.v2.u64 {%0, %1}, [%2];" : "=l"(a), "=l"(b) : "r"(s));
}

// ---------------------------------------------------------------------------
// CSR build
// ---------------------------------------------------------------------------
__global__ void k_zero_cd(int n) {
    int i = blockIdx.x * blockDim.x + threadIdx.x;
    if (i < n) { g_cnt[i] = 0; g_deg[i] = 0.0f; }
}

__global__ void k_count(const int* __restrict__ ei,
                        const float* __restrict__ ew, int E) {
    int e = blockIdx.x * blockDim.x + threadIdx.x;
    if (e < E) {
        int c = ei[E + e];
        atomicAdd(&g_cnt[c], 1);
        atomicAdd(&g_deg[c], ew[e]);
    }
}

__global__ void k_dis(int n) {
    int i = blockIdx.x * blockDim.x + threadIdx.x;
    if (i < n) g_dis[i] = rsqrtf(g_deg[i] + 1.0f);   // +1 = self-loop weight
}

// exclusive scan, stage 1: 256-element chunks
__global__ void k_scan_local(int n) {
    __shared__ int s[256];
    int tid = threadIdx.x;
    int gid = blockIdx.x * 256 + tid;
    int v = (gid < n) ? g_cnt[gid] : 0;
    s[tid] = v;
    #pragma unroll
    for (int off = 1; off < 256; off <<= 1) {
        __syncthreads();
        int t = (tid >= off) ? s[tid - off] : 0;
        __syncthreads();
        s[tid] += t;
    }
    __syncthreads();
    if (gid < n) g_excl[gid] = s[tid] - v;
    if (tid == 255) g_bsum[blockIdx.x] = s[255];
}

// stage 2: scan block sums (<=512)
__global__ void k_scan_bsum(int nb) {
    __shared__ int s[512];
    int tid = threadIdx.x;
    int v = (tid < nb) ? g_bsum[tid] : 0;
    s[tid] = v;
    #pragma unroll
    for (int off = 1; off < 512; off <<= 1) {
        __syncthreads();
        int t = (tid >= off) ? s[tid - off] : 0;
        __syncthreads();
        s[tid] += t;
    }
    __syncthreads();
    if (tid < nb) g_boff[tid] = s[tid] - v;
}

// stage 3: combine, init rowptr + fill cursor
__global__ void k_scan_add(int n) {
    int i = blockIdx.x * blockDim.x + threadIdx.x;
    if (i < n) {
        int v = g_excl[i] + g_boff[i >> 8];
        g_rowptr[i] = v;
        g_fill[i]   = v;
    }
}

// scatter edges into CSR; precompute nrm = dis[src]*w*dis[dst]
__global__ void k_fill(const int* __restrict__ ei,
                       const float* __restrict__ ew, int E) {
    int e = blockIdx.x * blockDim.x + threadIdx.x;
    if (e >= E) return;
    int r = ei[e];
    int c = ei[E + e];
    float nrm = g_dis[r] * ew[e] * g_dis[c];
    int pos = atomicAdd(&g_fill[c], 1);
    g_edge[pos] = make_float2(__int_as_float(r), nrm);
}

// ---------------------------------------------------------------------------
// GEMM1: g_h1[N,64] = x[N,256] @ W1[256,64]   (R6 winner config)
// 256 thr, tile 128 rows x 64 cols, 8 rows x 4 cols per thread via FFMA2.
// ---------------------------------------------------------------------------
#define G1_ROWS 128
#define G1_KCH  32

__global__ void k_gemm1(const float* __restrict__ x,
                        const float* __restrict__ W1) {
    __shared__ float xs[G1_KCH][G1_ROWS];   // 16 KB, k-major
    __shared__ float ws[G1_KCH][F_HID];     // 8 KB,  k-major

    int t    = threadIdx.x;
    int row0 = blockIdx.x * G1_ROWS;
    int tx   = t & 15;        // col group: cols tx*4 .. +3
    int ty   = t >> 4;        // row group: rows ty*8 .. +7

    unsigned long long acc2[4][4];
    #pragma unroll
    for (int p = 0; p < 4; p++)
        #pragma unroll
        for (int j = 0; j < 4; j++) acc2[p][j] = f2pack(0.0f, 0.0f);

    for (int kc = 0; kc < F_IN / G1_KCH; kc++) {
        const float4* w4 = (const float4*)(W1 + kc * G1_KCH * F_HID);
        ((float4*)ws)[t]       = w4[t];
        ((float4*)ws)[t + 256] = w4[t + 256];
        #pragma unroll
        for (int j = 0; j < 4; j++) {
            int idx = t + j * 256;
            int r   = idx & 127;
            int kq  = idx >> 7;
            int gr  = row0 + r;
            if (gr >= N_NODES) gr = N_NODES - 1;
            float4 v = *(const float4*)(x + (size_t)gr * F_IN + kc * G1_KCH + kq * 4);
            xs[kq * 4 + 0][r] = v.x;
            xs[kq * 4 + 1][r] = v.y;
            xs[kq * 4 + 2][r] = v.z;
            xs[kq * 4 + 3][r] = v.w;
        }
        __syncthreads();

        #pragma unroll
        for (int kk = 0; kk < G1_KCH; kk++) {
            unsigned long long ap0, ap1, ap2, ap3;
            lds_v2u64(ap0, ap1, &xs[kk][ty * 8]);
            lds_v2u64(ap2, ap3, &xs[kk][ty * 8 + 4]);
            float4 b = *(const float4*)&ws[kk][tx * 4];
            unsigned long long bd0 = f2pack(b.x, b.x);
            unsigned long long bd1 = f2pack(b.y, b.y);
            unsigned long long bd2 = f2pack(b.z, b.z);
            unsigned long long bd3 = f2pack(b.w, b.w);
            fma2(acc2[0][0], ap0, bd0); fma2(acc2[0][1], ap0, bd1);
            fma2(acc2[0][2], ap0, bd2); fma2(acc2[0][3], ap0, bd3);
            fma2(acc2[1][0], ap1, bd0); fma2(acc2[1][1], ap1, bd1);
            fma2(acc2[1][2], ap1, bd2); fma2(acc2[1][3], ap1, bd3);
            fma2(acc2[2][0], ap2, bd0); fma2(acc2[2][1], ap2, bd1);
            fma2(acc2[2][2], ap2, bd2); fma2(acc2[2][3], ap2, bd3);
            fma2(acc2[3][0], ap3, bd0); fma2(acc2[3][1], ap3, bd1);
            fma2(acc2[3][2], ap3, bd2); fma2(acc2[3][3], ap3, bd3);
        }
        __syncthreads();
    }

    #pragma unroll
    for (int p = 0; p < 4; p++) {
        float lo0, hi0, lo1, hi1, lo2, hi2, lo3, hi3;
        f2unpack(acc2[p][0], lo0, hi0);
        f2unpack(acc2[p][1], lo1, hi1);
        f2unpack(acc2[p][2], lo2, hi2);
        f2unpack(acc2[p][3], lo3, hi3);
        int gr0 = row0 + ty * 8 + 2 * p;
        if (gr0 < N_NODES)
            *(float4*)(g_h1 + (size_t)gr0 * F_HID + tx * 4) =
                make_float4(lo0, lo1, lo2, lo3);
        if (gr0 + 1 < N_NODES)
            *(float4*)(g_h1 + (size_t)(gr0 + 1) * F_HID + tx * 4) =
                make_float4(hi0, hi1, hi2, hi3);
    }
}

// ---------------------------------------------------------------------------
// Layer-1 CSR aggregation: 16 threads per node, gather-only, no atomics.
// Fuses self-loop + bias + relu.
// ---------------------------------------------------------------------------
__global__ void k_agg1_csr(const float* __restrict__ b1) {
    int idx  = blockIdx.x * blockDim.x + threadIdx.x;
    int node = idx >> 4;
    int c    = idx & 15;
    if (node >= N_NODES) return;
    int beg = g_rowptr[node];
    int cnt = g_cnt[node];
    float di = g_dis[node];

    float4 acc = make_float4(0.f, 0.f, 0.f, 0.f);
    int j = 0;
    for (; j + 1 < cnt; j += 2) {
        float2 e0 = g_edge[beg + j];
        float2 e1 = g_edge[beg + j + 1];
        int s0 = __float_as_int(e0.x);
        int s1 = __float_as_int(e1.x);
        float4 v0 = *(const float4*)(g_h1 + (size_t)s0 * F_HID + c * 4);
        float4 v1 = *(const float4*)(g_h1 + (size_t)s1 * F_HID + c * 4);
        acc.x += e0.y * v0.x + e1.y * v1.x;
        acc.y += e0.y * v0.y + e1.y * v1.y;
        acc.z += e0.y * v0.z + e1.y * v1.z;
        acc.w += e0.y * v0.w + e1.y * v1.w;
    }
    if (j < cnt) {
        float2 e0 = g_edge[beg + j];
        int s0 = __float_as_int(e0.x);
        float4 v0 = *(const float4*)(g_h1 + (size_t)s0 * F_HID + c * 4);
        acc.x += e0.y * v0.x;
        acc.y += e0.y * v0.y;
        acc.z += e0.y * v0.z;
        acc.w += e0.y * v0.w;
    }

    float s2 = di * di;
    float4 h = *(const float4*)(g_h1 + (size_t)node * F_HID + c * 4);
    float4 b = ((const float4*)b1)[c];
    float4 o;
    o.x = fmaxf(acc.x + s2 * h.x + b.x, 0.0f);
    o.y = fmaxf(acc.y + s2 * h.y + b.y, 0.0f);
    o.z = fmaxf(acc.z + s2 * h.z + b.z, 0.0f);
    o.w = fmaxf(acc.w + s2 * h.w + b.w, 0.0f);
    *(float4*)(g_agg1 + (size_t)node * F_HID + c * 4) = o;
}

// ---------------------------------------------------------------------------
// GEMM2: g_h2[N,40] = g_agg1[N,64] @ W2[64,40]   (R6 config)
// ---------------------------------------------------------------------------
#define G2_ROWS 128

__global__ void k_gemm2(const float* __restrict__ W2) {
    __shared__ float rs[F_HID][G2_ROWS];   // 32 KB, k-major
    __shared__ float ws2[F_HID][F_OUT];    // 10 KB

    int t    = threadIdx.x;
    int row0 = blockIdx.x * G2_ROWS;
    int tx   = t & 7;         // cols tx*5 .. +4
    int ty   = t >> 3;        // rows ty*4 .. +3

    #pragma unroll
    for (int j = 0; j < 3; j++) {
        int i = t + j * 256;
        if (i < 640) ((float4*)ws2)[i] = ((const float4*)W2)[i];
    }
    #pragma unroll
    for (int j = 0; j < 8; j++) {
        int idx = t + j * 256;
        int r   = idx & 127;
        int kq  = idx >> 7;
        int gr  = row0 + r;
        if (gr >= N_NODES) gr = N_NODES - 1;
        float4 v = *(const float4*)(g_agg1 + (size_t)gr * F_HID + kq * 4);
        rs[kq * 4 + 0][r] = v.x;
        rs[kq * 4 + 1][r] = v.y;
        rs[kq * 4 + 2][r] = v.z;
        rs[kq * 4 + 3][r] = v.w;
    }
    __syncthreads();

    unsigned long long acc2[2][5];
    #pragma unroll
    for (int p = 0; p < 2; p++)
        #pragma unroll
        for (int j = 0; j < 5; j++) acc2[p][j] = f2pack(0.0f, 0.0f);

    #pragma unroll
    for (int kk = 0; kk < F_HID; kk++) {
        unsigned long long ap0, ap1;
        lds_v2u64(ap0, ap1, &rs[kk][ty * 4]);
        const float* wrow = &ws2[kk][tx * 5];
        #pragma unroll
        for (int j = 0; j < 5; j++) {
            float bj = wrow[j];
            unsigned long long bd = f2pack(bj, bj);
            fma2(acc2[0][j], ap0, bd);
            fma2(acc2[1][j], ap1, bd);
        }
    }

    #pragma unroll
    for (int p = 0; p < 2; p++) {
        float lo[5], hi[5];
        #pragma unroll
        for (int j = 0; j < 5; j++) f2unpack(acc2[p][j], lo[j], hi[j]);
        int gr0 = row0 + ty * 4 + 2 * p;
        if (gr0 < N_NODES) {
            float* o = g_h2 + (size_t)gr0 * F_OUT + tx * 5;
            #pragma unroll
            for (int j = 0; j < 5; j++) o[j] = lo[j];
        }
        if (gr0 + 1 < N_NODES) {
            float* o = g_h2 + (size_t)(gr0 + 1) * F_OUT + tx * 5;
            #pragma unroll
            for (int j = 0; j < 5; j++) o[j] = hi[j];
        }
    }
}

// ---------------------------------------------------------------------------
// Layer-2 CSR aggregation: 16 threads/node (10 active), fuses b2 + self-loop.
// ---------------------------------------------------------------------------
__global__ void k_agg2_csr(const float* __restrict__ b2,
                           float* __restrict__ out) {
    int idx  = blockIdx.x * blockDim.x + threadIdx.x;
    int node = idx >> 4;
    int c    = idx & 15;
    if (node >= N_NODES || c >= 10) return;
    int beg = g_rowptr[node];
    int cnt = g_cnt[node];
    float di = g_dis[node];

    float4 acc = make_float4(0.f, 0.f, 0.f, 0.f);
    int j = 0;
    for (; j + 1 < cnt; j += 2) {
        float2 e0 = g_edge[beg + j];
        float2 e1 = g_edge[beg + j + 1];
        int s0 = __float_as_int(e0.x);
        int s1 = __float_as_int(e1.x);
        float4 v0 = *(const float4*)(g_h2 + (size_t)s0 * F_OUT + c * 4);
        float4 v1 = *(const float4*)(g_h2 + (size_t)s1 * F_OUT + c * 4);
        acc.x += e0.y * v0.x + e1.y * v1.x;
        acc.y += e0.y * v0.y + e1.y * v1.y;
        acc.z += e0.y * v0.z + e1.y * v1.z;
        acc.w += e0.y * v0.w + e1.y * v1.w;
    }
    if (j < cnt) {
        float2 e0 = g_edge[beg + j];
        int s0 = __float_as_int(e0.x);
        float4 v0 = *(const float4*)(g_h2 + (size_t)s0 * F_OUT + c * 4);
        acc.x += e0.y * v0.x;
        acc.y += e0.y * v0.y;
        acc.z += e0.y * v0.z;
        acc.w += e0.y * v0.w;
    }

    float s2 = di * di;
    float4 h = *(const float4*)(g_h2 + (size_t)node * F_OUT + c * 4);
    float4 b = ((const float4*)b2)[c];
    float4 o;
    o.x = acc.x + s2 * h.x + b.x;
    o.y = acc.y + s2 * h.y + b.y;
    o.z = acc.z + s2 * h.z + b.z;
    o.w = acc.w + s2 * h.w + b.w;
    *(float4*)(out + (size_t)node * F_OUT + c * 4) = o;
}

// ---------------------------------------------------------------------------
extern "C" void kernel_launch(void* const* d_in, const int* in_sizes, int n_in,
                              void* d_out, int out_size) {
    const float* x  = (const float*)d_in[0];
    const int*   ei = (const int*)d_in[1];
    const float* ew = (const float*)d_in[2];
    const float* W1 = (const float*)d_in[3];
    const float* b1 = (const float*)d_in[4];
    const float* W2 = (const float*)d_in[5];
    const float* b2 = (const float*)d_in[6];
    float* out = (float*)d_out;

    int N = in_sizes[0] / F_IN;     // 100000
    int E = in_sizes[2];            // 1600000
    int nblk = (N + 255) / 256;     // 391

    // CSR build + normalization
    k_zero_cd<<<nblk, 256>>>(N);
    k_count<<<(E + 255) / 256, 256>>>(ei, ew, E);
    k_dis<<<nblk, 256>>>(N);
    k_scan_local<<<nblk, 256>>>(N);
    k_scan_bsum<<<1, 512>>>(nblk);
    k_scan_add<<<nblk, 256>>>(N);
    k_fill<<<(E + 255) / 256, 256>>>(ei, ew, E);

    // layer 1
    k_gemm1<<<(N + G1_ROWS - 1) / G1_ROWS, 256>>>(x, W1);
    {
        long long items = (long long)N * 16;
        k_agg1_csr<<<(int)((items + 255) / 256), 256>>>(b1);
    }

    // layer 2
    k_gemm2<<<(N + G2_ROWS - 1) / G2_ROWS, 256>>>(W2);
    {
        long long items = (long long)N * 16;
        k_agg2_csr<<<(int)((items + 255) / 256), 256>>>(b2, out);
    }
}